// round 3
// baseline (speedup 1.0000x reference)
#include <cuda_runtime.h>
#include <cuda_bf16.h>
#include <math.h>
#include <cstdint>

// Problem constants
#define B_    4
#define T_    2048
#define DM    1024
#define NH    16
#define DH    64
#define ROWS  (B_ * T_)          // 8192
#define QKV_N (3 * DM)           // 3072

// Scratch (device globals: allocation-free)
__device__ float g_qkv[ROWS * QKV_N];    // [8192, 3072]
__device__ float g_attn[ROWS * DM];      // [8192, 1024]

// ===========================================================================
// helpers
// ===========================================================================
__device__ __forceinline__ uint32_t smem_u32(const void* p) {
    uint32_t a;
    asm("{ .reg .u64 t; cvta.to.shared.u64 t, %1; cvt.u32.u64 %0, t; }"
        : "=r"(a) : "l"(p));
    return a;
}
__device__ __forceinline__ uint32_t f2tf32(float v) {
    uint32_t u;
    asm("cvt.rna.tf32.f32 %0, %1;" : "=r"(u) : "f"(v));
    return u;
}
__device__ __forceinline__ void lds_v2(uint32_t& x, uint32_t& y, uint32_t addr) {
    asm volatile("ld.shared.v2.b32 {%0,%1}, [%2];" : "=r"(x), "=r"(y) : "r"(addr));
}
__device__ __forceinline__ void mma_tf32(float* d, const uint32_t* a, const uint32_t* b) {
    asm volatile(
        "mma.sync.aligned.m16n8k8.row.col.f32.tf32.tf32.f32 "
        "{%0,%1,%2,%3}, {%4,%5,%6,%7}, {%8,%9}, {%0,%1,%2,%3};"
        : "+f"(d[0]), "+f"(d[1]), "+f"(d[2]), "+f"(d[3])
        : "r"(a[0]), "r"(a[1]), "r"(a[2]), "r"(a[3]), "r"(b[0]), "r"(b[1]));
}

// k-interleaved + XOR-swizzled smem index (rows of 32 floats = 16 8B slots).
// element (row, k) with k in [0,32): group g = k>>3, cq = k&3, hi = (k>>2)&1
//   8B slot s = g*4 + cq, swizzled s' = s ^ (row&7)
//   float index = row*32 + s'*2 + hi
// A-fragment v2 load at (row, g, cq=lane&3) returns {col=cq, col=cq+4} = {a0,a2}.
__device__ __forceinline__ int sw_idx(int row, int g, int cq) {
    int s = (g * 4 + cq) ^ (row & 7);
    return row * 32 + s * 2;
}

// ===========================================================================
// tf32 mma.sync GEMM: C[M,N] = A[M,K] @ B[K,N], fp32 in/out.
// CTA 128x128, BK=32, 256 threads (8 warps, 2x4 warp grid, 64x32 warp tiles).
// ===========================================================================
__global__ __launch_bounds__(256) void gemm_mma_kernel(
    const float* __restrict__ A, const float* __restrict__ Bm,
    float* __restrict__ C, int N, int K)
{
    __shared__ float As[128 * 32];
    __shared__ float Bs[128 * 32];

    const int tid  = threadIdx.x;
    const int lane = tid & 31;
    const int wid  = tid >> 5;
    const int wm   = wid >> 2;          // 0..1
    const int wn   = wid & 3;           // 0..3
    const int tig  = lane & 3;          // thread-in-group
    const int grp  = lane >> 2;         // group id 0..7
    const int bm = blockIdx.y * 128;
    const int bn = blockIdx.x * 128;

    const uint32_t as_base = smem_u32(As);
    const uint32_t bs_base = smem_u32(Bs);

    float acc[4][4][4];
#pragma unroll
    for (int i = 0; i < 4; ++i)
#pragma unroll
        for (int j = 0; j < 4; ++j)
#pragma unroll
            for (int r = 0; r < 4; ++r) acc[i][j][r] = 0.f;

    // B loader mapping: n = tid&127, k = (tid>>7)*16 + kk
    const int bln = tid & 127;
    const int blk = (tid >> 7) * 16;

    for (int k0 = 0; k0 < K; k0 += 32) {
        // ---- A: 128 rows x 32 cols ----
#pragma unroll
        for (int i = 0; i < 4; ++i) {
            int idx = tid + i * 256;       // 0..1023 float4 slots
            int row = idx >> 3;
            int c4  = (idx & 7) * 4;       // 0,4,...,28
            float4 v = *(const float4*)(A + (size_t)(bm + row) * K + k0 + c4);
            int g  = c4 >> 3;
            int hi = (c4 >> 2) & 1;
            As[sw_idx(row, g, 0) + hi] = __uint_as_float(f2tf32(v.x));
            As[sw_idx(row, g, 1) + hi] = __uint_as_float(f2tf32(v.y));
            As[sw_idx(row, g, 2) + hi] = __uint_as_float(f2tf32(v.z));
            As[sw_idx(row, g, 3) + hi] = __uint_as_float(f2tf32(v.w));
        }
        // ---- B: transpose to Bs[n][k] ----
        {
            const float* Bp = Bm + (size_t)(k0 + blk) * N + bn + bln;
#pragma unroll
            for (int kk = 0; kk < 16; ++kk) {
                float v = Bp[(size_t)kk * N];
                int k  = blk + kk;
                int g  = k >> 3;
                int cq = k & 3;
                int hi = (k >> 2) & 1;
                Bs[sw_idx(bln, g, cq) + hi] = __uint_as_float(f2tf32(v));
            }
        }
        __syncthreads();

        // ---- compute: 4 k-steps x (4 m-tiles x 4 n-tiles) mma ----
#pragma unroll
        for (int g = 0; g < 4; ++g) {
            uint32_t af[4][4];
#pragma unroll
            for (int mt = 0; mt < 4; ++mt) {
                int r0 = wm * 64 + mt * 16 + grp;
                lds_v2(af[mt][0], af[mt][2], as_base + 4u * sw_idx(r0,     g, tig));
                lds_v2(af[mt][1], af[mt][3], as_base + 4u * sw_idx(r0 + 8, g, tig));
            }
#pragma unroll
            for (int nt = 0; nt < 4; ++nt) {
                uint32_t bf[2];
                int n0 = wn * 32 + nt * 8 + grp;
                lds_v2(bf[0], bf[1], bs_base + 4u * sw_idx(n0, g, tig));
#pragma unroll
                for (int mt = 0; mt < 4; ++mt)
                    mma_tf32(acc[mt][nt], af[mt], bf);
            }
        }
        __syncthreads();
    }

    // ---- epilogue ----
#pragma unroll
    for (int mt = 0; mt < 4; ++mt) {
        int r = bm + wm * 64 + mt * 16 + grp;
#pragma unroll
        for (int nt = 0; nt < 4; ++nt) {
            int c = bn + wn * 32 + nt * 8 + 2 * tig;
            float2 v0 = make_float2(acc[mt][nt][0], acc[mt][nt][1]);
            float2 v1 = make_float2(acc[mt][nt][2], acc[mt][nt][3]);
            *(float2*)(C + (size_t)r * N + c)       = v0;
            *(float2*)(C + (size_t)(r + 8) * N + c) = v1;
        }
    }
}

// ---------------------------------------------------------------------------
// Flash attention (no mask), fp32 SIMT (unchanged; known-good).
// ---------------------------------------------------------------------------
#define FSTR 68
#define FSM  (64 * FSTR)

__global__ __launch_bounds__(256) void flash_kernel(
    const float* __restrict__ qkv, float* __restrict__ attn)
{
    extern __shared__ float sm[];
    float* Ks = sm;
    float* Vs = sm + FSM;
    float* Ps = sm + 2 * FSM;   // also Q staging

    const int tid = threadIdx.x;
    const int qt  = blockIdx.x;
    const int bh  = blockIdx.y;
    const int b   = bh >> 4;
    const int h   = bh & 15;

    const int r       = tid >> 2;
    const int quarter = tid & 3;

#pragma unroll
    for (int i = 0; i < 4; ++i) {
        int idx = tid + i * 256;
        int row = idx >> 4;
        int c4  = idx & 15;
        const float4 v = *(const float4*)&qkv[
            (size_t)(b * T_ + qt * 64 + row) * QKV_N + h * DH + c4 * 4];
        *(float4*)&Ps[row * FSTR + c4 * 4] = v;
    }
    __syncthreads();

    float q[64];
#pragma unroll
    for (int d = 0; d < 64; ++d) q[d] = Ps[r * FSTR + d] * 0.125f;
    __syncthreads();

    float O[16];
#pragma unroll
    for (int i = 0; i < 16; ++i) O[i] = 0.f;
    float m = -INFINITY;
    float l = 0.f;

    for (int j = 0; j < T_ / 64; ++j) {
#pragma unroll
        for (int i = 0; i < 4; ++i) {
            int idx = tid + i * 256;
            int row = idx >> 4;
            int c4  = idx & 15;
            size_t g = (size_t)(b * T_ + j * 64 + row) * QKV_N + h * DH + c4 * 4;
            float4 kv = *(const float4*)&qkv[g + DM];
            float4 vv = *(const float4*)&qkv[g + 2 * DM];
            *(float4*)&Ks[row * FSTR + c4 * 4] = kv;
            *(float4*)&Vs[row * FSTR + c4 * 4] = vv;
        }
        __syncthreads();

        float s[16];
#pragma unroll
        for (int c = 0; c < 16; ++c) {
            const float4* krow = (const float4*)&Ks[(quarter * 16 + c) * FSTR];
            float a0 = 0.f, a1 = 0.f;
#pragma unroll
            for (int d4 = 0; d4 < 16; d4 += 2) {
                float4 k0 = krow[d4];
                float4 k1 = krow[d4 + 1];
                a0 += q[4*d4+0]*k0.x + q[4*d4+1]*k0.y + q[4*d4+2]*k0.z + q[4*d4+3]*k0.w;
                a1 += q[4*d4+4]*k1.x + q[4*d4+5]*k1.y + q[4*d4+6]*k1.z + q[4*d4+7]*k1.w;
            }
            s[c] = a0 + a1;
        }

        float mloc = s[0];
#pragma unroll
        for (int c = 1; c < 16; ++c) mloc = fmaxf(mloc, s[c]);
        mloc = fmaxf(mloc, __shfl_xor_sync(0xffffffffu, mloc, 1));
        mloc = fmaxf(mloc, __shfl_xor_sync(0xffffffffu, mloc, 2));

        float mnew = fmaxf(m, mloc);
        float corr = __expf(m - mnew);

        float lloc = 0.f;
#pragma unroll
        for (int c = 0; c < 16; ++c) {
            float p = __expf(s[c] - mnew);
            Ps[r * FSTR + quarter * 16 + c] = p;
            lloc += p;
        }
        lloc += __shfl_xor_sync(0xffffffffu, lloc, 1);
        lloc += __shfl_xor_sync(0xffffffffu, lloc, 2);

        l = l * corr + lloc;
        m = mnew;
#pragma unroll
        for (int i = 0; i < 16; ++i) O[i] *= corr;
        __syncwarp();

#pragma unroll 4
        for (int k = 0; k < 64; ++k) {
            float p = Ps[r * FSTR + k];
            const float4* vrow = (const float4*)&Vs[k * FSTR + quarter * 16];
#pragma unroll
            for (int c4 = 0; c4 < 4; ++c4) {
                float4 vv = vrow[c4];
                O[c4 * 4 + 0] += p * vv.x;
                O[c4 * 4 + 1] += p * vv.y;
                O[c4 * 4 + 2] += p * vv.z;
                O[c4 * 4 + 3] += p * vv.w;
            }
        }
        __syncthreads();
    }

    const float inv = 1.f / l;
    float* orow = attn + (size_t)(b * T_ + qt * 64 + r) * DM + h * DH + quarter * 16;
#pragma unroll
    for (int c4 = 0; c4 < 4; ++c4) {
        float4 o;
        o.x = O[c4 * 4 + 0] * inv;
        o.y = O[c4 * 4 + 1] * inv;
        o.z = O[c4 * 4 + 2] * inv;
        o.w = O[c4 * 4 + 3] * inv;
        *(float4*)(orow + c4 * 4) = o;
    }
}

// ---------------------------------------------------------------------------
extern "C" void kernel_launch(void* const* d_in, const int* in_sizes, int n_in,
                              void* d_out, int out_size)
{
    const float* x      = (const float*)d_in[0];   // [4,2048,1024]
    const float* w_qkv  = (const float*)d_in[1];   // [1024,3072]
    const float* w_proj = (const float*)d_in[2];   // [1024,1024]
    float* out = (float*)d_out;                    // [4,2048,1024]

    float* qkvbuf = nullptr;
    float* attnbuf = nullptr;
    cudaGetSymbolAddress((void**)&qkvbuf, g_qkv);
    cudaGetSymbolAddress((void**)&attnbuf, g_attn);

    static bool attr_set = false;
    if (!attr_set) {
        cudaFuncSetAttribute(flash_kernel,
                             cudaFuncAttributeMaxDynamicSharedMemorySize,
                             3 * FSM * (int)sizeof(float));
        attr_set = true;
    }

    // 1) QKV projection: [8192,1024] @ [1024,3072]  (tf32 mma.sync)
    {
        dim3 grid(QKV_N / 128, ROWS / 128);
        gemm_mma_kernel<<<grid, 256>>>(x, w_qkv, qkvbuf, QKV_N, DM);
    }

    // 2) Attention (fp32 SIMT flash)
    {
        dim3 grid(T_ / 64, B_ * NH);
        flash_kernel<<<grid, 256, 3 * FSM * (int)sizeof(float)>>>(qkvbuf, attnbuf);
    }

    // 3) Output projection: [8192,1024] @ [1024,1024]  (tf32 mma.sync)
    {
        dim3 grid(DM / 128, ROWS / 128);
        gemm_mma_kernel<<<grid, 256>>>(attnbuf, w_proj, out, DM, DM);
    }
}

// round 4
// speedup vs baseline: 6.8486x; 6.8486x over previous
#include <cuda_runtime.h>
#include <cuda_bf16.h>
#include <math.h>
#include <cstdint>

// Problem constants
#define B_    4
#define T_    2048
#define DM    1024
#define NH    16
#define DH    64
#define ROWS  (B_ * T_)          // 8192
#define QKV_N (3 * DM)           // 3072

// Scratch (device globals: allocation-free)
__device__ float g_qkv[ROWS * QKV_N];    // [8192, 3072]
__device__ float g_attn[ROWS * DM];      // [8192, 1024]

// ===========================================================================
// helpers
// ===========================================================================
__device__ __forceinline__ uint32_t smem_u32(const void* p) {
    uint32_t a;
    asm("{ .reg .u64 t; cvta.to.shared.u64 t, %1; cvt.u32.u64 %0, t; }"
        : "=r"(a) : "l"(p));
    return a;
}
__device__ __forceinline__ uint32_t f2tf32(float v) {
    uint32_t u;
    asm("cvt.rna.tf32.f32 %0, %1;" : "=r"(u) : "f"(v));
    return u;
}
__device__ __forceinline__ void lds_v2(uint32_t& x, uint32_t& y, uint32_t addr) {
    asm volatile("ld.shared.v2.b32 {%0,%1}, [%2];" : "=r"(x), "=r"(y) : "r"(addr));
}
__device__ __forceinline__ void mma_tf32(float* d, const uint32_t* a, const uint32_t* b) {
    asm volatile(
        "mma.sync.aligned.m16n8k8.row.col.f32.tf32.tf32.f32 "
        "{%0,%1,%2,%3}, {%4,%5,%6,%7}, {%8,%9}, {%0,%1,%2,%3};"
        : "+f"(d[0]), "+f"(d[1]), "+f"(d[2]), "+f"(d[3])
        : "r"(a[0]), "r"(a[1]), "r"(a[2]), "r"(a[3]), "r"(b[0]), "r"(b[1]));
}

// k-interleaved + XOR-swizzled smem index (rows of 32 floats = 16 8B slots).
__device__ __forceinline__ int sw_idx(int row, int g, int cq) {
    int s = (g * 4 + cq) ^ (row & 7);
    return row * 32 + s * 2;
}

// ===========================================================================
// tf32 mma.sync GEMM: C[M,N] = A[M,K] @ B[K,N], fp32 in/out. (unchanged R3)
// CTA 128x128, BK=32, 256 threads (8 warps, 2x4 warp grid, 64x32 warp tiles).
// ===========================================================================
__global__ __launch_bounds__(256) void gemm_mma_kernel(
    const float* __restrict__ A, const float* __restrict__ Bm,
    float* __restrict__ C, int N, int K)
{
    __shared__ float As[128 * 32];
    __shared__ float Bs[128 * 32];

    const int tid  = threadIdx.x;
    const int lane = tid & 31;
    const int wid  = tid >> 5;
    const int wm   = wid >> 2;
    const int wn   = wid & 3;
    const int tig  = lane & 3;
    const int grp  = lane >> 2;
    const int bm = blockIdx.y * 128;
    const int bn = blockIdx.x * 128;

    const uint32_t as_base = smem_u32(As);
    const uint32_t bs_base = smem_u32(Bs);

    float acc[4][4][4];
#pragma unroll
    for (int i = 0; i < 4; ++i)
#pragma unroll
        for (int j = 0; j < 4; ++j)
#pragma unroll
            for (int r = 0; r < 4; ++r) acc[i][j][r] = 0.f;

    const int bln = tid & 127;
    const int blk = (tid >> 7) * 16;

    for (int k0 = 0; k0 < K; k0 += 32) {
#pragma unroll
        for (int i = 0; i < 4; ++i) {
            int idx = tid + i * 256;
            int row = idx >> 3;
            int c4  = (idx & 7) * 4;
            float4 v = *(const float4*)(A + (size_t)(bm + row) * K + k0 + c4);
            int g  = c4 >> 3;
            int hi = (c4 >> 2) & 1;
            As[sw_idx(row, g, 0) + hi] = __uint_as_float(f2tf32(v.x));
            As[sw_idx(row, g, 1) + hi] = __uint_as_float(f2tf32(v.y));
            As[sw_idx(row, g, 2) + hi] = __uint_as_float(f2tf32(v.z));
            As[sw_idx(row, g, 3) + hi] = __uint_as_float(f2tf32(v.w));
        }
        {
            const float* Bp = Bm + (size_t)(k0 + blk) * N + bn + bln;
#pragma unroll
            for (int kk = 0; kk < 16; ++kk) {
                float v = Bp[(size_t)kk * N];
                int k  = blk + kk;
                int g  = k >> 3;
                int cq = k & 3;
                int hi = (k >> 2) & 1;
                Bs[sw_idx(bln, g, cq) + hi] = __uint_as_float(f2tf32(v));
            }
        }
        __syncthreads();

#pragma unroll
        for (int g = 0; g < 4; ++g) {
            uint32_t af[4][4];
#pragma unroll
            for (int mt = 0; mt < 4; ++mt) {
                int r0 = wm * 64 + mt * 16 + grp;
                lds_v2(af[mt][0], af[mt][2], as_base + 4u * sw_idx(r0,     g, tig));
                lds_v2(af[mt][1], af[mt][3], as_base + 4u * sw_idx(r0 + 8, g, tig));
            }
#pragma unroll
            for (int nt = 0; nt < 4; ++nt) {
                uint32_t bf[2];
                int n0 = wn * 32 + nt * 8 + grp;
                lds_v2(bf[0], bf[1], bs_base + 4u * sw_idx(n0, g, tig));
#pragma unroll
                for (int mt = 0; mt < 4; ++mt)
                    mma_tf32(acc[mt][nt], af[mt], bf);
            }
        }
        __syncthreads();
    }

#pragma unroll
    for (int mt = 0; mt < 4; ++mt) {
        int r = bm + wm * 64 + mt * 16 + grp;
#pragma unroll
        for (int nt = 0; nt < 4; ++nt) {
            int c = bn + wn * 32 + nt * 8 + 2 * tig;
            float2 v0 = make_float2(acc[mt][nt][0], acc[mt][nt][1]);
            float2 v1 = make_float2(acc[mt][nt][2], acc[mt][nt][3]);
            *(float2*)(C + (size_t)r * N + c)       = v0;
            *(float2*)(C + (size_t)(r + 8) * N + c) = v1;
        }
    }
}

// ===========================================================================
// Flash attention on tensor cores (tf32 mma.sync), no mask.
// Grid: (T/128, B*NH). Block 256 (8 warps). Warp w owns Q rows [16w,16w+16).
// smem (dynamic): Ps[128][68] (Q staging + P), Ks[64][68], Vs[64][68].
// All smem values stored as tf32 bit patterns.
// ===========================================================================
#define FSTR 68
#define FLASH_SMEM ((128 * FSTR + 2 * 64 * FSTR) * 4)

__global__ __launch_bounds__(256) void flash_mma_kernel(
    const float* __restrict__ qkv, float* __restrict__ attn)
{
    extern __shared__ float sm[];
    float* Ps = sm;                       // 128 x FSTR
    float* Ks = sm + 128 * FSTR;          // 64 x FSTR
    float* Vs = Ks + 64 * FSTR;           // 64 x FSTR

    const int tid  = threadIdx.x;
    const int lane = tid & 31;
    const int wid  = tid >> 5;
    const int grp  = lane >> 2;
    const int tig  = lane & 3;
    const int qt = blockIdx.x;
    const int bh = blockIdx.y;
    const int b  = bh >> 4;
    const int h  = bh & 15;

    const int r0 = wid * 16 + grp;        // this thread's first Q row (tile-local)

    // ---- stage Q tile (scaled, tf32) into Ps ----
    const size_t qbase = (size_t)(b * T_ + qt * 128) * QKV_N + h * DH;
#pragma unroll
    for (int i = 0; i < 8; ++i) {
        int idx = tid + i * 256;          // 2048 float4 slots
        int row = idx >> 4;
        int c4  = idx & 15;
        float4 v = *(const float4*)&qkv[qbase + (size_t)row * QKV_N + c4 * 4];
        float* p = &Ps[row * FSTR + c4 * 4];
        p[0] = __uint_as_float(f2tf32(v.x * 0.125f));
        p[1] = __uint_as_float(f2tf32(v.y * 0.125f));
        p[2] = __uint_as_float(f2tf32(v.z * 0.125f));
        p[3] = __uint_as_float(f2tf32(v.w * 0.125f));
    }
    __syncthreads();

    // ---- Q fragments into registers ----
    uint32_t qf[8][4];
#pragma unroll
    for (int kc = 0; kc < 8; ++kc) {
        qf[kc][0] = __float_as_uint(Ps[r0 * FSTR + 8 * kc + tig]);
        qf[kc][1] = __float_as_uint(Ps[(r0 + 8) * FSTR + 8 * kc + tig]);
        qf[kc][2] = __float_as_uint(Ps[r0 * FSTR + 8 * kc + tig + 4]);
        qf[kc][3] = __float_as_uint(Ps[(r0 + 8) * FSTR + 8 * kc + tig + 4]);
    }
    // (no barrier needed: Ps rows [16w,16w+16) are warp-private from here on)

    float Oa[8][4];
#pragma unroll
    for (int nt = 0; nt < 8; ++nt)
#pragma unroll
        for (int r = 0; r < 4; ++r) Oa[nt][r] = 0.f;
    float mrun0 = -INFINITY, mrun1 = -INFINITY;
    float lrun0 = 0.f, lrun1 = 0.f;

    for (int j = 0; j < T_ / 64; ++j) {
        // ---- load K, V tiles (tf32 bits) ----
        const size_t kbase = (size_t)(b * T_ + j * 64) * QKV_N + h * DH;
#pragma unroll
        for (int i = 0; i < 4; ++i) {
            int idx = tid + i * 256;      // 1024 float4 slots
            int row = idx >> 4;
            int c4  = idx & 15;
            size_t g = kbase + (size_t)row * QKV_N + c4 * 4;
            float4 kv = *(const float4*)&qkv[g + DM];
            float4 vv = *(const float4*)&qkv[g + 2 * DM];
            float* pk = &Ks[row * FSTR + c4 * 4];
            float* pv = &Vs[row * FSTR + c4 * 4];
            pk[0] = __uint_as_float(f2tf32(kv.x));
            pk[1] = __uint_as_float(f2tf32(kv.y));
            pk[2] = __uint_as_float(f2tf32(kv.z));
            pk[3] = __uint_as_float(f2tf32(kv.w));
            pv[0] = __uint_as_float(f2tf32(vv.x));
            pv[1] = __uint_as_float(f2tf32(vv.y));
            pv[2] = __uint_as_float(f2tf32(vv.z));
            pv[3] = __uint_as_float(f2tf32(vv.w));
        }
        __syncthreads();

        // ---- S = Q @ K^T ----
        float Sa[8][4];
#pragma unroll
        for (int nt = 0; nt < 8; ++nt)
#pragma unroll
            for (int r = 0; r < 4; ++r) Sa[nt][r] = 0.f;
#pragma unroll
        for (int kc = 0; kc < 8; ++kc) {
#pragma unroll
            for (int nt = 0; nt < 8; ++nt) {
                uint32_t bf[2];
                bf[0] = __float_as_uint(Ks[(8 * nt + grp) * FSTR + 8 * kc + tig]);
                bf[1] = __float_as_uint(Ks[(8 * nt + grp) * FSTR + 8 * kc + tig + 4]);
                mma_tf32(Sa[nt], qf[kc], bf);
            }
        }

        // ---- online softmax (rows r0 via c0/c1, r0+8 via c2/c3) ----
        float ml0 = -INFINITY, ml1 = -INFINITY;
#pragma unroll
        for (int nt = 0; nt < 8; ++nt) {
            ml0 = fmaxf(ml0, fmaxf(Sa[nt][0], Sa[nt][1]));
            ml1 = fmaxf(ml1, fmaxf(Sa[nt][2], Sa[nt][3]));
        }
        ml0 = fmaxf(ml0, __shfl_xor_sync(0xffffffffu, ml0, 1));
        ml0 = fmaxf(ml0, __shfl_xor_sync(0xffffffffu, ml0, 2));
        ml1 = fmaxf(ml1, __shfl_xor_sync(0xffffffffu, ml1, 1));
        ml1 = fmaxf(ml1, __shfl_xor_sync(0xffffffffu, ml1, 2));

        float mnew0 = fmaxf(mrun0, ml0);
        float mnew1 = fmaxf(mrun1, ml1);
        float corr0 = __expf(mrun0 - mnew0);
        float corr1 = __expf(mrun1 - mnew1);

        float ls0 = 0.f, ls1 = 0.f;
#pragma unroll
        for (int nt = 0; nt < 8; ++nt) {
            float p00 = __expf(Sa[nt][0] - mnew0);
            float p01 = __expf(Sa[nt][1] - mnew0);
            float p10 = __expf(Sa[nt][2] - mnew1);
            float p11 = __expf(Sa[nt][3] - mnew1);
            ls0 += p00 + p01;
            ls1 += p10 + p11;
            float2 w0, w1;
            w0.x = __uint_as_float(f2tf32(p00));
            w0.y = __uint_as_float(f2tf32(p01));
            w1.x = __uint_as_float(f2tf32(p10));
            w1.y = __uint_as_float(f2tf32(p11));
            *(float2*)&Ps[r0 * FSTR + 8 * nt + 2 * tig]       = w0;
            *(float2*)&Ps[(r0 + 8) * FSTR + 8 * nt + 2 * tig] = w1;
        }
        ls0 += __shfl_xor_sync(0xffffffffu, ls0, 1);
        ls0 += __shfl_xor_sync(0xffffffffu, ls0, 2);
        ls1 += __shfl_xor_sync(0xffffffffu, ls1, 1);
        ls1 += __shfl_xor_sync(0xffffffffu, ls1, 2);

        lrun0 = lrun0 * corr0 + ls0;
        lrun1 = lrun1 * corr1 + ls1;
        mrun0 = mnew0;
        mrun1 = mnew1;
#pragma unroll
        for (int nt = 0; nt < 8; ++nt) {
            Oa[nt][0] *= corr0;
            Oa[nt][1] *= corr0;
            Oa[nt][2] *= corr1;
            Oa[nt][3] *= corr1;
        }
        __syncwarp();

        // ---- O += P @ V ----
#pragma unroll
        for (int kc = 0; kc < 8; ++kc) {
            uint32_t af[4];
            af[0] = __float_as_uint(Ps[r0 * FSTR + 8 * kc + tig]);
            af[1] = __float_as_uint(Ps[(r0 + 8) * FSTR + 8 * kc + tig]);
            af[2] = __float_as_uint(Ps[r0 * FSTR + 8 * kc + tig + 4]);
            af[3] = __float_as_uint(Ps[(r0 + 8) * FSTR + 8 * kc + tig + 4]);
#pragma unroll
            for (int nt = 0; nt < 8; ++nt) {
                uint32_t bf[2];
                bf[0] = __float_as_uint(Vs[(8 * kc + tig) * FSTR + 8 * nt + grp]);
                bf[1] = __float_as_uint(Vs[(8 * kc + tig + 4) * FSTR + 8 * nt + grp]);
                mma_tf32(Oa[nt], af, bf);
            }
        }
        __syncthreads();   // Ks/Vs reused next iteration
    }

    // ---- epilogue ----
    const float inv0 = 1.f / lrun0;
    const float inv1 = 1.f / lrun1;
    float* o0 = attn + (size_t)(b * T_ + qt * 128 + r0) * DM + h * DH;
    float* o1 = attn + (size_t)(b * T_ + qt * 128 + r0 + 8) * DM + h * DH;
#pragma unroll
    for (int nt = 0; nt < 8; ++nt) {
        float2 v0 = make_float2(Oa[nt][0] * inv0, Oa[nt][1] * inv0);
        float2 v1 = make_float2(Oa[nt][2] * inv1, Oa[nt][3] * inv1);
        *(float2*)(o0 + 8 * nt + 2 * tig) = v0;
        *(float2*)(o1 + 8 * nt + 2 * tig) = v1;
    }
}

// ---------------------------------------------------------------------------
extern "C" void kernel_launch(void* const* d_in, const int* in_sizes, int n_in,
                              void* d_out, int out_size)
{
    const float* x      = (const float*)d_in[0];   // [4,2048,1024]
    const float* w_qkv  = (const float*)d_in[1];   // [1024,3072]
    const float* w_proj = (const float*)d_in[2];   // [1024,1024]
    float* out = (float*)d_out;                    // [4,2048,1024]

    float* qkvbuf = nullptr;
    float* attnbuf = nullptr;
    cudaGetSymbolAddress((void**)&qkvbuf, g_qkv);
    cudaGetSymbolAddress((void**)&attnbuf, g_attn);

    static bool attr_set = false;
    if (!attr_set) {
        cudaFuncSetAttribute(flash_mma_kernel,
                             cudaFuncAttributeMaxDynamicSharedMemorySize,
                             FLASH_SMEM);
        attr_set = true;
    }

    // 1) QKV projection: [8192,1024] @ [1024,3072]  (tf32 mma.sync)
    {
        dim3 grid(QKV_N / 128, ROWS / 128);
        gemm_mma_kernel<<<grid, 256>>>(x, w_qkv, qkvbuf, QKV_N, DM);
    }

    // 2) Attention (tf32 mma.sync flash)
    {
        dim3 grid(T_ / 128, B_ * NH);
        flash_mma_kernel<<<grid, 256, FLASH_SMEM>>>(qkvbuf, attnbuf);
    }

    // 3) Output projection: [8192,1024] @ [1024,1024]  (tf32 mma.sync)
    {
        dim3 grid(DM / 128, ROWS / 128);
        gemm_mma_kernel<<<grid, 256>>>(attnbuf, w_proj, out, DM, DM);
    }
}